// round 9
// baseline (speedup 1.0000x reference)
#include <cuda_runtime.h>
#include <cuda_bf16.h>

// LatentMap, R9: broadcast (cross-LDG) phase 1 + proven R4/R6 phase 2.
//
// Phase 1 (NEW): the warp iterates its 32 queries one at a time. Every lane
//   loads the SAME addresses (query position, neighbor_map entry, 4 neighbor
//   positions) -> each LDG touches exactly one 128B line -> 1 wavefront at
//   the 1.0 cyc/wf cross-LDG rate, instead of lane-parallel scatter where
//   one LDG spans ~32 lines and pays the 2.07 cyc/wf within-LDG replay rate.
//   Weight math is replicated across lanes (fma/alu/MUFU pipes are nearly
//   idle). The owning lane (lane == i) keeps nb/w in registers; after the
//   loop one lane-parallel smem store (0.25 wf/query) publishes them.
//
// Phase 2 (unchanged): warp sweeps 32 queries 4 at a time; lane -> (query
//   sub = lane>>3, feature quad = (lane&7)*4): 2 LDS.128, 4 coalesced
//   LDG.128 gathers, 1 STG.128 spanning 512B, FFMA.

#define IMG 1024
#define EMB 32
#define WARPS_PER_BLOCK 8
#define QUERIES_PER_WARP 32

__global__ void __launch_bounds__(WARPS_PER_BLOCK * 32, 8) latent_map_kernel(
    const float2* __restrict__ position,      // [N_Q]
    const float2* __restrict__ positions,     // [N_PTS]
    const int4*   __restrict__ neighbor_map,  // [IMG*IMG]
    const float*  __restrict__ embeddings,    // [N_PTS, EMB]
    const float*  __restrict__ harmonics,     // [EMB]
    float*        __restrict__ out,           // [N_Q, EMB]
    int n_q)
{
    __shared__ int4   s_nb[WARPS_PER_BLOCK][QUERIES_PER_WARP];
    __shared__ float4 s_w [WARPS_PER_BLOCK][QUERIES_PER_WARP];

    const int warp = threadIdx.x >> 5;
    const int lane = threadIdx.x & 31;
    const int qbase = (blockIdx.x * WARPS_PER_BLOCK + warp) * QUERIES_PER_WARP;

    const int n_live = min(QUERIES_PER_WARP, n_q - qbase);  // uniform per warp

    // ---- Phase 1: broadcast iteration; all-uniform (1-line) gathers ----
    int4   r_nb;
    float4 r_w;

    #pragma unroll 4
    for (int i = 0; i < QUERIES_PER_WARP; ++i) {
        if (i < n_live) {
            const int q = qbase + i;
            const float2 p = position[q];                 // uniform, 1 wf
            const int ix = (int)floorf(p.x);
            const int iy = (int)floorf(p.y);
            const int4 nb = neighbor_map[ix * IMG + iy];  // uniform, 1 wf

            const float2 p0 = positions[nb.x];            // uniform, 1 wf
            const float2 p1 = positions[nb.y];            // uniform, 1 wf
            const float2 p2 = positions[nb.z];            // uniform, 1 wf
            const float2 p3 = positions[nb.w];            // uniform, 1 wf

            const float fx = (float)ix, fy = (float)iy;
            float dx, dy;
            dx = p0.x - fx; dy = p0.y - fy;
            const float d0 = sqrtf(dx * dx + dy * dy);
            dx = p1.x - fx; dy = p1.y - fy;
            const float d1 = sqrtf(dx * dx + dy * dy);
            dx = p2.x - fx; dy = p2.y - fy;
            const float d2 = sqrtf(dx * dx + dy * dy);
            dx = p3.x - fx; dy = p3.y - fy;
            const float d3 = sqrtf(dx * dx + dy * dy);

            const float rs = 1.0f / (d0 + d1 + d2 + d3 + 1e-8f);
            float4 w;
            w.x = 1.0f - d0 * rs;
            w.y = 1.0f - d1 * rs;
            w.z = 1.0f - d2 * rs;
            w.w = 1.0f - d3 * rs;

            if (lane == i) { r_nb = nb; r_w = w; }  // owning lane keeps it
        }
    }

    // Publish to smem with ONE lane-parallel pair of STS.128 (0.25 wf/query).
    if (lane < n_live) {
        s_nb[warp][lane] = r_nb;
        s_w [warp][lane] = r_w;
    }
    __syncwarp();

    // ---- Phase 2: 4 queries per iteration; lane -> (query sub, feature quad)
    const int sub = lane >> 3;        // 0..3
    const int fq  = (lane & 7) * 4;   // 0,4,...,28

    const float4 h4 = *(const float4*)&harmonics[fq];

    if (n_live == QUERIES_PER_WARP) {
        // Hot path: no per-iteration predicates.
        #pragma unroll
        for (int i = 0; i < QUERIES_PER_WARP; i += 4) {
            const int4   nb = s_nb[warp][i + sub];  // LDS.128
            const float4 w  = s_w [warp][i + sub];  // LDS.128

            const float4 e0 = __ldg((const float4*)&embeddings[(long)nb.x * EMB + fq]);
            const float4 e1 = __ldg((const float4*)&embeddings[(long)nb.y * EMB + fq]);
            const float4 e2 = __ldg((const float4*)&embeddings[(long)nb.z * EMB + fq]);
            const float4 e3 = __ldg((const float4*)&embeddings[(long)nb.w * EMB + fq]);

            float4 acc;
            acc.x = w.x * e0.x + w.y * e1.x + w.z * e2.x + w.w * e3.x;
            acc.y = w.x * e0.y + w.y * e1.y + w.z * e2.y + w.w * e3.y;
            acc.z = w.x * e0.z + w.y * e1.z + w.z * e2.z + w.w * e3.z;
            acc.w = w.x * e0.w + w.y * e1.w + w.z * e2.w + w.w * e3.w;

            acc.x *= h4.x; acc.y *= h4.y; acc.z *= h4.z; acc.w *= h4.w;

            *(float4*)&out[(long)(qbase + i + sub) * EMB + fq] = acc;
        }
    } else {
        #pragma unroll
        for (int i = 0; i < QUERIES_PER_WARP; i += 4) {
            const int q = qbase + i + sub;
            if (q < n_q) {
                const int4   nb = s_nb[warp][i + sub];
                const float4 w  = s_w [warp][i + sub];

                const float4 e0 = __ldg((const float4*)&embeddings[(long)nb.x * EMB + fq]);
                const float4 e1 = __ldg((const float4*)&embeddings[(long)nb.y * EMB + fq]);
                const float4 e2 = __ldg((const float4*)&embeddings[(long)nb.z * EMB + fq]);
                const float4 e3 = __ldg((const float4*)&embeddings[(long)nb.w * EMB + fq]);

                float4 acc;
                acc.x = w.x * e0.x + w.y * e1.x + w.z * e2.x + w.w * e3.x;
                acc.y = w.x * e0.y + w.y * e1.y + w.z * e2.y + w.w * e3.y;
                acc.z = w.x * e0.z + w.y * e1.z + w.z * e2.z + w.w * e3.z;
                acc.w = w.x * e0.w + w.y * e1.w + w.z * e2.w + w.w * e3.w;

                acc.x *= h4.x; acc.y *= h4.y; acc.z *= h4.z; acc.w *= h4.w;

                *(float4*)&out[(long)q * EMB + fq] = acc;
            }
        }
    }
}

extern "C" void kernel_launch(void* const* d_in, const int* in_sizes, int n_in,
                              void* d_out, int out_size)
{
    const float2* position     = (const float2*)d_in[0];
    const float2* positions    = (const float2*)d_in[1];
    const int4*   neighbor_map = (const int4*)d_in[2];
    const float*  embeddings   = (const float*)d_in[3];
    const float*  harmonics    = (const float*)d_in[4];
    float*        out          = (float*)d_out;

    const int n_q = in_sizes[0] / 2;
    const int queries_per_block = WARPS_PER_BLOCK * QUERIES_PER_WARP; // 256
    const int grid = (n_q + queries_per_block - 1) / queries_per_block;
    latent_map_kernel<<<grid, WARPS_PER_BLOCK * 32>>>(
        position, positions, neighbor_map, embeddings, harmonics, out, n_q);
}

// round 10
// speedup vs baseline: 2.4511x; 2.4511x over previous
#include <cuda_runtime.h>
#include <cuda_bf16.h>

// LatentMap, warp-cooperative two-phase fused kernel (R6 structure, R10 tune).
//
// Phase 1: lane l computes per-query scalars (neighbor indices + normalized
//          inverse-distance weights) for query qbase + l, once, -> smem.
// Phase 2: warp sweeps its 32 queries 4 at a time; lane -> (query sub =
//          lane>>3, feature quad = (lane&7)*4): 2 LDS.128, 4 coalesced
//          LDG.128 gathers, 1 STG.128 spanning 512B, ~20 FFMA.
//
// R10 changes vs R6 (both cheap, orthogonal):
//  1. Output stores use st.global.wt (__stwt): the 128MB write-once output
//     no longer write-allocates in L2, protecting the ~30MB gather working
//     set (embeddings read ~40x/row) from eviction.
//  2. 128-thread blocks, 16 blocks/SM: same 64-warp occupancy, finer CTA
//     granularity -> less cross-CTA completion spread.

#define IMG 1024
#define EMB 32
#define WARPS_PER_BLOCK 4
#define QUERIES_PER_WARP 32

__global__ void __launch_bounds__(WARPS_PER_BLOCK * 32, 16) latent_map_kernel(
    const float2* __restrict__ position,      // [N_Q]
    const float2* __restrict__ positions,     // [N_PTS]
    const int4*   __restrict__ neighbor_map,  // [IMG*IMG]
    const float*  __restrict__ embeddings,    // [N_PTS, EMB]
    const float*  __restrict__ harmonics,     // [EMB]
    float*        __restrict__ out,           // [N_Q, EMB]
    int n_q)
{
    __shared__ int4   s_nb[WARPS_PER_BLOCK][QUERIES_PER_WARP];
    __shared__ float4 s_w [WARPS_PER_BLOCK][QUERIES_PER_WARP];

    const int warp = threadIdx.x >> 5;
    const int lane = threadIdx.x & 31;
    const int qbase = (blockIdx.x * WARPS_PER_BLOCK + warp) * QUERIES_PER_WARP;

    const bool full_tile = (qbase + QUERIES_PER_WARP) <= n_q;

    // ---- Phase 1: one query per lane, scalar work done exactly once ----
    {
        const int q = qbase + lane;
        if (full_tile || q < n_q) {
            const float2 p = position[q];
            const int ix = (int)floorf(p.x);
            const int iy = (int)floorf(p.y);
            const int4 nb = neighbor_map[ix * IMG + iy];

            const float2 p0 = positions[nb.x];
            const float2 p1 = positions[nb.y];
            const float2 p2 = positions[nb.z];
            const float2 p3 = positions[nb.w];

            const float fx = (float)ix, fy = (float)iy;
            float dx, dy;
            dx = p0.x - fx; dy = p0.y - fy;
            const float d0 = sqrtf(dx * dx + dy * dy);
            dx = p1.x - fx; dy = p1.y - fy;
            const float d1 = sqrtf(dx * dx + dy * dy);
            dx = p2.x - fx; dy = p2.y - fy;
            const float d2 = sqrtf(dx * dx + dy * dy);
            dx = p3.x - fx; dy = p3.y - fy;
            const float d3 = sqrtf(dx * dx + dy * dy);

            const float rs = 1.0f / (d0 + d1 + d2 + d3 + 1e-8f);
            float4 w;
            w.x = 1.0f - d0 * rs;
            w.y = 1.0f - d1 * rs;
            w.z = 1.0f - d2 * rs;
            w.w = 1.0f - d3 * rs;

            s_nb[warp][lane] = nb;
            s_w [warp][lane] = w;
        }
    }
    __syncwarp();

    // ---- Phase 2: 4 queries per iteration; lane -> (query sub, feature quad)
    const int sub = lane >> 3;        // 0..3
    const int fq  = (lane & 7) * 4;   // 0,4,...,28

    const float4 h4 = *(const float4*)&harmonics[fq];

    if (full_tile) {
        // Hot path: no per-iteration predicates.
        #pragma unroll
        for (int i = 0; i < QUERIES_PER_WARP; i += 4) {
            const int4   nb = s_nb[warp][i + sub];  // LDS.128
            const float4 w  = s_w [warp][i + sub];  // LDS.128

            const float4 e0 = __ldg((const float4*)&embeddings[(long)nb.x * EMB + fq]);
            const float4 e1 = __ldg((const float4*)&embeddings[(long)nb.y * EMB + fq]);
            const float4 e2 = __ldg((const float4*)&embeddings[(long)nb.z * EMB + fq]);
            const float4 e3 = __ldg((const float4*)&embeddings[(long)nb.w * EMB + fq]);

            float4 acc;
            acc.x = w.x * e0.x + w.y * e1.x + w.z * e2.x + w.w * e3.x;
            acc.y = w.x * e0.y + w.y * e1.y + w.z * e2.y + w.w * e3.y;
            acc.z = w.x * e0.z + w.y * e1.z + w.z * e2.z + w.w * e3.z;
            acc.w = w.x * e0.w + w.y * e1.w + w.z * e2.w + w.w * e3.w;

            acc.x *= h4.x; acc.y *= h4.y; acc.z *= h4.z; acc.w *= h4.w;

            // Streaming store: don't write-allocate the output in L2.
            __stwt((float4*)&out[(long)(qbase + i + sub) * EMB + fq], acc);
        }
    } else {
        #pragma unroll
        for (int i = 0; i < QUERIES_PER_WARP; i += 4) {
            const int q = qbase + i + sub;
            if (q < n_q) {
                const int4   nb = s_nb[warp][i + sub];
                const float4 w  = s_w [warp][i + sub];

                const float4 e0 = __ldg((const float4*)&embeddings[(long)nb.x * EMB + fq]);
                const float4 e1 = __ldg((const float4*)&embeddings[(long)nb.y * EMB + fq]);
                const float4 e2 = __ldg((const float4*)&embeddings[(long)nb.z * EMB + fq]);
                const float4 e3 = __ldg((const float4*)&embeddings[(long)nb.w * EMB + fq]);

                float4 acc;
                acc.x = w.x * e0.x + w.y * e1.x + w.z * e2.x + w.w * e3.x;
                acc.y = w.x * e0.y + w.y * e1.y + w.z * e2.y + w.w * e3.y;
                acc.z = w.x * e0.z + w.y * e1.z + w.z * e2.z + w.w * e3.z;
                acc.w = w.x * e0.w + w.y * e1.w + w.z * e2.w + w.w * e3.w;

                acc.x *= h4.x; acc.y *= h4.y; acc.z *= h4.z; acc.w *= h4.w;

                __stwt((float4*)&out[(long)q * EMB + fq], acc);
            }
        }
    }
}

extern "C" void kernel_launch(void* const* d_in, const int* in_sizes, int n_in,
                              void* d_out, int out_size)
{
    const float2* position     = (const float2*)d_in[0];
    const float2* positions    = (const float2*)d_in[1];
    const int4*   neighbor_map = (const int4*)d_in[2];
    const float*  embeddings   = (const float*)d_in[3];
    const float*  harmonics    = (const float*)d_in[4];
    float*        out          = (float*)d_out;

    const int n_q = in_sizes[0] / 2;
    const int queries_per_block = WARPS_PER_BLOCK * QUERIES_PER_WARP; // 128
    const int grid = (n_q + queries_per_block - 1) / queries_per_block;
    latent_map_kernel<<<grid, WARPS_PER_BLOCK * 32>>>(
        position, positions, neighbor_map, embeddings, harmonics, out, n_q);
}